// round 14
// baseline (speedup 1.0000x reference)
#include <cuda_runtime.h>
#include <stdint.h>

// out[k,l] = sum_j mitchell_mul(x[k,j], weight[l,j]) + bias[l]
// Mitchell approx multiply == integer add of offset float bit patterns:
//   packed(v) = (sign<<31) | max(bits(|v|) - 0x1FC00000, 0)
//   mitchell(a,b) = reinterpret_float(packed(a) + packed(b))
// (low fields < 2^30 for these inputs -> no carry into the sign bit; signs XOR)
//
// R14: occupancy push on the R13 winner. SPLITS=16 -> 512 CTAs so 4 CTAs/SM
// materialize; __launch_bounds__(256,4) (regs<=64) by dropping the explicit
// k-pipeline (8 warps/SMSP cover LDS latency instead). Same fused REDG.128
// epilogue into bias-prefilled out.

#define NROWS 512
#define MROWS 512
#define KDIM  1024
#define SPLITS 16
#define KC (KDIM / SPLITS)   // 64 k per split
#define BK 16
#define BM 128               // x rows per CTA
#define BN 64                // w rows per CTA
#define PADM (BM + 4)
#define PADN (BN + 4)
#define TM 8
#define TN 4
#define NSTAGE (KC / BK)     // 4

__device__ __forceinline__ unsigned int pack1(unsigned int b) {
    unsigned int mag = b & 0x7FFFFFFFu;
    unsigned int low = (mag > 0x1FC00000u) ? (mag - 0x1FC00000u) : 0u;
    return (b & 0x80000000u) | low;
}

__global__ __launch_bounds__(256) void prefill_kernel(
    const float* __restrict__ bias, float* __restrict__ out) {
    int i4 = blockIdx.x * blockDim.x + threadIdx.x;   // 0..65535 float4s
    reinterpret_cast<float4*>(out)[i4] =
        reinterpret_cast<const float4*>(bias)[i4 & (MROWS / 4 - 1)];
}

__global__ __launch_bounds__(256, 4) void mitchell_mm_kernel(
    const uint4* __restrict__ xq, const uint4* __restrict__ wq,
    float* __restrict__ out) {
    __shared__ unsigned int Xs[2][BK][PADM];   // double-buffered [k][row]
    __shared__ unsigned int Ws[2][BK][PADN];

    const int tid = threadIdx.x;            // 256 threads: 16 x 16
    const int tx = tid & 15;                // col group (TN=4)
    const int ty = tid >> 4;                // row group (TM=8)
    const int rowBase = blockIdx.y * BM;
    const int colBase = blockIdx.x * BN;
    const int kBase   = blockIdx.z * KC;
    const int K4 = KDIM / 4;

    float acc[TM][TN];
#pragma unroll
    for (int i = 0; i < TM; i++)
#pragma unroll
        for (int j = 0; j < TN; j++) acc[i][j] = 0.0f;

    // Staging (BK=16): X tile 128x16 = 512 uint4 (2/thread),
    //                  W tile  64x16 = 256 uint4 (1/thread).
    const int xrow = tid >> 2;              // 0..63 (+64 for v=1)
    const int kq   = tid & 3;               // k-quad 0..3

    uint4 px[2], pw;
    auto gload = [&](int kk) {
        int gk4 = (kBase + kk) / 4 + kq;
#pragma unroll
        for (int v = 0; v < 2; v++)
            px[v] = xq[(rowBase + xrow + 64 * v) * K4 + gk4];
        pw = wq[(colBase + xrow) * K4 + gk4];
    };

    auto sstore = [&](int b) {
#pragma unroll
        for (int v = 0; v < 2; v++) {
            int r = xrow + 64 * v;
            Xs[b][kq * 4 + 0][r] = pack1(px[v].x);
            Xs[b][kq * 4 + 1][r] = pack1(px[v].y);
            Xs[b][kq * 4 + 2][r] = pack1(px[v].z);
            Xs[b][kq * 4 + 3][r] = pack1(px[v].w);
        }
        Ws[b][kq * 4 + 0][xrow] = pack1(pw.x);
        Ws[b][kq * 4 + 1][xrow] = pack1(pw.y);
        Ws[b][kq * 4 + 2][xrow] = pack1(pw.z);
        Ws[b][kq * 4 + 3][xrow] = pack1(pw.w);
    };

    gload(0);
    sstore(0);
    __syncthreads();

#pragma unroll 1
    for (int s = 0; s < NSTAGE; s++) {
        const int buf = s & 1;
        if (s + 1 < NSTAGE) gload((s + 1) * BK);   // LDG latency under compute

#pragma unroll
        for (int k = 0; k < BK; k++) {
            uint4 a0 = *reinterpret_cast<const uint4*>(&Xs[buf][k][ty * TM]);
            uint4 a1 = *reinterpret_cast<const uint4*>(&Xs[buf][k][ty * TM + 4]);
            uint4 b0 = *reinterpret_cast<const uint4*>(&Ws[buf][k][tx * TN]);
            unsigned int a[TM] = {a0.x, a0.y, a0.z, a0.w, a1.x, a1.y, a1.z, a1.w};
            unsigned int b[TN] = {b0.x, b0.y, b0.z, b0.w};
#pragma unroll
            for (int i = 0; i < TM; i++)
#pragma unroll
                for (int j = 0; j < TN; j++)
                    acc[i][j] += __uint_as_float(a[i] + b[j]);
        }

        if (s + 1 < NSTAGE) sstore(buf ^ 1);   // fill other buffer (bar'd last stage)
        __syncthreads();
    }

    // Fused split-K reduction: vector float4 atomics (REDG.128, fire-and-forget)
    // into the bias-prefilled output.
#pragma unroll
    for (int i = 0; i < TM; i++) {
        int r = rowBase + ty * TM + i;
        atomicAdd(reinterpret_cast<float4*>(&out[r * MROWS + colBase + tx * TN]),
                  make_float4(acc[i][0], acc[i][1], acc[i][2], acc[i][3]));
    }
}

extern "C" void kernel_launch(void* const* d_in, const int* in_sizes, int n_in,
                              void* d_out, int out_size) {
    const float* x    = (const float*)d_in[0];
    const float* w    = (const float*)d_in[1];
    const float* bias = (const float*)d_in[2];
    float* out = (float*)d_out;

    prefill_kernel<<<NROWS * MROWS / 4 / 256, 256>>>(bias, out);

    dim3 grid(MROWS / BN, NROWS / BM, SPLITS);   // (8,4,16) = 512 CTAs, 4/SM
    mitchell_mm_kernel<<<grid, 256>>>((const uint4*)x, (const uint4*)w, out);
}

// round 15
// speedup vs baseline: 1.0611x; 1.0611x over previous
#include <cuda_runtime.h>
#include <stdint.h>

// out[k,l] = sum_j mitchell_mul(x[k,j], weight[l,j]) + bias[l]
// Mitchell approx multiply == integer add of offset float bit patterns:
//   packed(v) = (sign<<31) | max(bits(|v|) - 0x1FC00000, 0)
//   mitchell(a,b) = reinterpret_float(packed(a) + packed(b))
// (low fields < 2^30 for these inputs -> no carry into the sign bit; signs XOR)
//
// R15: balance round. 148 SMs = 4*37, so power-of-2 grids are stuck at 86.5%
// wave efficiency. Split K over grid.z=37 (25 slices of 28 k + 12 of 27):
// grid (8,4,37) = 1184 CTAs = exactly 2 waves at 4 CTAs/SM. Slices with 27 k
// zero their 28th smem plane (packed 0 + 0 -> +0.0f) so the k-loop is a
// uniform 28 iterations. Single-stage smem; cross-CTA overlap hides LDG.

#define NROWS 512
#define MROWS 512
#define KDIM  1024
#define ZSLICES 37
#define KMAX 28              // k's per slice (27 or 28; loop always runs 28)
#define BM 128               // x rows per CTA
#define BN 64                // w rows per CTA
#define PADM (BM + 4)        // 132 words/row: 16B-aligned rows for LDS.128
#define PADN (BN + 4)        // 68
#define TM 8
#define TN 4

__device__ __forceinline__ unsigned int pack1(unsigned int b) {
    unsigned int mag = b & 0x7FFFFFFFu;
    unsigned int low = (mag > 0x1FC00000u) ? (mag - 0x1FC00000u) : 0u;
    return (b & 0x80000000u) | low;
}

__global__ __launch_bounds__(256) void prefill_kernel(
    const float* __restrict__ bias, float* __restrict__ out) {
    int i4 = blockIdx.x * blockDim.x + threadIdx.x;   // 0..65535 float4s
    reinterpret_cast<float4*>(out)[i4] =
        reinterpret_cast<const float4*>(bias)[i4 & (MROWS / 4 - 1)];
}

__global__ __launch_bounds__(256, 4) void mitchell_mm_kernel(
    const float* __restrict__ x, const float* __restrict__ w,
    float* __restrict__ out) {
    __shared__ unsigned int Xs[KMAX][PADM];   // [k][row]  14784 B
    __shared__ unsigned int Ws[KMAX][PADN];   //            7616 B

    const int tid = threadIdx.x;            // 256 threads: 16 x 16
    const int tx = tid & 15;                // col group (TN=4)
    const int ty = tid >> 4;                // row group (TM=8)
    const int rowBase = blockIdx.y * BM;
    const int colBase = blockIdx.x * BN;
    const int z = blockIdx.z;
    // 25 slices of 28 k, then 12 slices of 27 k (25*28 + 12*27 = 1024).
    const int kBase = (z < 25) ? 28 * z : 27 * z + 25;
    const int kc    = (z < 25) ? 28 : 27;

    // ---- Staging: whole slice at once. Thread (r0, c): c = k index 0..31,
    //      r0 = row group. Predicated scalar loads (zBase may be unaligned).
    const int c  = tid & 31;                // k column 0..31
    const int r0 = tid >> 5;                // 0..7
    const bool cv = (c < kc);
    const int gk = kBase + (cv ? c : 0);    // clamped (in-bounds) when invalid

    if (c < KMAX) {
#pragma unroll
        for (int it = 0; it < 16; it++) {   // X: 128 rows
            int row = r0 + it * 8;
            unsigned int v = cv
                ? pack1(__float_as_uint(x[(rowBase + row) * KDIM + gk])) : 0u;
            Xs[c][row] = v;
        }
#pragma unroll
        for (int it = 0; it < 8; it++) {    // W: 64 rows
            int row = r0 + it * 8;
            unsigned int v = cv
                ? pack1(__float_as_uint(w[(colBase + row) * KDIM + gk])) : 0u;
            Ws[c][row] = v;
        }
    }
    __syncthreads();

    // ---- Uniform 28-iteration MAC loop.
    float acc[TM][TN];
#pragma unroll
    for (int i = 0; i < TM; i++)
#pragma unroll
        for (int j = 0; j < TN; j++) acc[i][j] = 0.0f;

#pragma unroll 4
    for (int k = 0; k < KMAX; k++) {
        uint4 a0 = *reinterpret_cast<const uint4*>(&Xs[k][ty * TM]);
        uint4 a1 = *reinterpret_cast<const uint4*>(&Xs[k][ty * TM + 4]);
        uint4 b0 = *reinterpret_cast<const uint4*>(&Ws[k][tx * TN]);
        unsigned int a[TM] = {a0.x, a0.y, a0.z, a0.w, a1.x, a1.y, a1.z, a1.w};
        unsigned int b[TN] = {b0.x, b0.y, b0.z, b0.w};
#pragma unroll
        for (int i = 0; i < TM; i++)
#pragma unroll
            for (int j = 0; j < TN; j++)
                acc[i][j] += __uint_as_float(a[i] + b[j]);
    }

    // ---- Fused split-K reduction: vector REDG.128 into bias-prefilled out.
#pragma unroll
    for (int i = 0; i < TM; i++) {
        int r = rowBase + ty * TM + i;
        atomicAdd(reinterpret_cast<float4*>(&out[r * MROWS + colBase + tx * TN]),
                  make_float4(acc[i][0], acc[i][1], acc[i][2], acc[i][3]));
    }
}

extern "C" void kernel_launch(void* const* d_in, const int* in_sizes, int n_in,
                              void* d_out, int out_size) {
    const float* x    = (const float*)d_in[0];
    const float* w    = (const float*)d_in[1];
    const float* bias = (const float*)d_in[2];
    float* out = (float*)d_out;

    prefill_kernel<<<NROWS * MROWS / 4 / 256, 256>>>(bias, out);

    dim3 grid(MROWS / BN, NROWS / BM, ZSLICES);   // (8,4,37) = 1184 CTAs
    mitchell_mm_kernel<<<grid, 256>>>(x, w, out);
}

// round 16
// speedup vs baseline: 1.1313x; 1.0662x over previous
#include <cuda_runtime.h>
#include <stdint.h>

// out[k,l] = sum_j mitchell_mul(x[k,j], weight[l,j]) + bias[l]
// Mitchell approx multiply == integer add of offset float bit patterns:
//   packed(v) = (sign<<31) | max(bits(|v|) - 0x1FC00000, 0)
//   mitchell(a,b) = reinterpret_float(packed(a) + packed(b))
// (low fields < 2^30 for these inputs -> no carry into the sign bit; signs XOR)
//
// R16: R15's perfect balance (grid.z=37 -> 1184 CTAs = 2 exact waves on
// 148 SMs) + R13's vectorized staging. Key: 1024 = 34*28 + 3*24, so every
// slice start is a multiple of 4 and uint4 loads are legal. kc=24 slices
// zero their last 4 smem planes (packed 0 + 0 -> +0.0f) so the MAC loop is
// a uniform 28 iterations. Fused REDG.128 epilogue into bias-prefilled out.

#define NROWS 512
#define MROWS 512
#define KDIM  1024
#define ZSLICES 37
#define KMAX 28              // k planes per slice (28 or 24 valid)
#define KQ   7               // quads per slice
#define BM 128               // x rows per CTA
#define BN 64                // w rows per CTA
#define PADM (BM + 4)
#define PADN (BN + 4)
#define TM 8
#define TN 4

__device__ __forceinline__ unsigned int pack1(unsigned int b) {
    unsigned int mag = b & 0x7FFFFFFFu;
    unsigned int low = (mag > 0x1FC00000u) ? (mag - 0x1FC00000u) : 0u;
    return (b & 0x80000000u) | low;
}

__global__ __launch_bounds__(256) void prefill_kernel(
    const float* __restrict__ bias, float* __restrict__ out) {
    int i4 = blockIdx.x * blockDim.x + threadIdx.x;   // 0..65535 float4s
    reinterpret_cast<float4*>(out)[i4] =
        reinterpret_cast<const float4*>(bias)[i4 & (MROWS / 4 - 1)];
}

__global__ __launch_bounds__(256, 4) void mitchell_mm_kernel(
    const uint4* __restrict__ xq, const uint4* __restrict__ wq,
    float* __restrict__ out) {
    __shared__ unsigned int Xs[KMAX][PADM];   // [k][row] 14784 B
    __shared__ unsigned int Ws[KMAX][PADN];   //           7616 B

    const int tid = threadIdx.x;            // 256 threads: 16 x 16
    const int tx = tid & 15;                // col group (TN=4)
    const int ty = tid >> 4;                // row group (TM=8)
    const int rowBase = blockIdx.y * BM;
    const int colBase = blockIdx.x * BN;
    const int z = blockIdx.z;
    // 34 slices of 28 k, then 3 slices of 24 k (34*28 + 3*24 = 1024).
    const int kBase = (z < 34) ? 28 * z : 952 + 24 * (z - 34);
    const int kcq   = (z < 34) ? 7 : 6;     // valid quads this slice
    const int K4 = KDIM / 4;
    const int g0 = kBase / 4;               // aligned: kBase % 4 == 0 always

    // ---- Vectorized staging: X rows {srow, srow+64}, W row srow; quads
    //      q = kq4 + 4t, t in {0,1}. Invalid quads (>= kcq) store zeros.
    const int srow = tid >> 2;              // 0..63
    const int kq4  = tid & 3;               // 0..3

    const uint4 zv = make_uint4(0u, 0u, 0u, 0u);
#pragma unroll
    for (int t = 0; t < 2; t++) {
        int q = kq4 + 4 * t;
        if (q < KQ) {
            bool valid = (q < kcq);
            uint4 x0 = valid ? xq[(rowBase + srow) * K4 + g0 + q] : zv;
            uint4 x1 = valid ? xq[(rowBase + srow + 64) * K4 + g0 + q] : zv;
            uint4 w0 = valid ? wq[(colBase + srow) * K4 + g0 + q] : zv;
            Xs[q * 4 + 0][srow] = pack1(x0.x);
            Xs[q * 4 + 1][srow] = pack1(x0.y);
            Xs[q * 4 + 2][srow] = pack1(x0.z);
            Xs[q * 4 + 3][srow] = pack1(x0.w);
            Xs[q * 4 + 0][srow + 64] = pack1(x1.x);
            Xs[q * 4 + 1][srow + 64] = pack1(x1.y);
            Xs[q * 4 + 2][srow + 64] = pack1(x1.z);
            Xs[q * 4 + 3][srow + 64] = pack1(x1.w);
            Ws[q * 4 + 0][srow] = pack1(w0.x);
            Ws[q * 4 + 1][srow] = pack1(w0.y);
            Ws[q * 4 + 2][srow] = pack1(w0.z);
            Ws[q * 4 + 3][srow] = pack1(w0.w);
        }
    }
    __syncthreads();

    // ---- Uniform 28-iteration MAC loop.
    float acc[TM][TN];
#pragma unroll
    for (int i = 0; i < TM; i++)
#pragma unroll
        for (int j = 0; j < TN; j++) acc[i][j] = 0.0f;

#pragma unroll 4
    for (int k = 0; k < KMAX; k++) {
        uint4 a0 = *reinterpret_cast<const uint4*>(&Xs[k][ty * TM]);
        uint4 a1 = *reinterpret_cast<const uint4*>(&Xs[k][ty * TM + 4]);
        uint4 b0 = *reinterpret_cast<const uint4*>(&Ws[k][tx * TN]);
        unsigned int a[TM] = {a0.x, a0.y, a0.z, a0.w, a1.x, a1.y, a1.z, a1.w};
        unsigned int b[TN] = {b0.x, b0.y, b0.z, b0.w};
#pragma unroll
        for (int i = 0; i < TM; i++)
#pragma unroll
            for (int j = 0; j < TN; j++)
                acc[i][j] += __uint_as_float(a[i] + b[j]);
    }

    // ---- Fused split-K reduction: vector REDG.128 into bias-prefilled out.
#pragma unroll
    for (int i = 0; i < TM; i++) {
        int r = rowBase + ty * TM + i;
        atomicAdd(reinterpret_cast<float4*>(&out[r * MROWS + colBase + tx * TN]),
                  make_float4(acc[i][0], acc[i][1], acc[i][2], acc[i][3]));
    }
}

extern "C" void kernel_launch(void* const* d_in, const int* in_sizes, int n_in,
                              void* d_out, int out_size) {
    const float* x    = (const float*)d_in[0];
    const float* w    = (const float*)d_in[1];
    const float* bias = (const float*)d_in[2];
    float* out = (float*)d_out;

    prefill_kernel<<<NROWS * MROWS / 4 / 256, 256>>>(bias, out);

    dim3 grid(MROWS / BN, NROWS / BM, ZSLICES);   // (8,4,37) = 1184 CTAs
    mitchell_mm_kernel<<<grid, 256>>>((const uint4*)x, (const uint4*)w, out);
}